// round 1
// baseline (speedup 1.0000x reference)
#include <cuda_runtime.h>
#include <math.h>

#define NPOS 392
#define KK   288          // K*K*IN_CAPS
#define OC   32
#define PS   16
#define OSZ  512          // OC*PS
#define CEPS 1e-8f
#define LN2PI 1.8378770664093453f
#define NTHREADS 512

// vote scratch: 392 * 288 * 512 floats = 231 MB
__device__ float g_votes[(size_t)NPOS * KK * OSZ];

extern __shared__ float smem[];

__global__ __launch_bounds__(NTHREADS, 1)
void convcaps_kernel(const float* __restrict__ x,
                     const float* __restrict__ wts,
                     const float* __restrict__ beta_u,
                     const float* __restrict__ beta_a,
                     float* __restrict__ out)
{
    const int n    = blockIdx.x;
    const int tid  = threadIdx.x;
    const int lane = tid & 31;
    const int wid  = tid >> 5;

    // ---- smem carve ----
    float* sP    = smem;            // 4608  poses [k][s]
    float* sA    = sP + KK*PS;      // 288   acts
    float* sR    = sA + KK;         // 9216  r [k][o]
    float* sMean = sR + KK*OC;      // 544   mean [o*17+s] (pad 17)
    float* sIv   = sMean + 544;     // 544   1/(2 std^2)
    float* sRsum = sIv + 544;       // 32
    float* sIRs  = sRsum + 32;      // 32
    float* sS1   = sIRs + 32;       // 32
    float* sAct  = sS1 + 32;        // 32
    float* sC    = sAct + 32;       // 32

    // ---- Phase 0: gather input tile (matches reference's reshape semantics) ----
    const int b = n / 49;
    const int m = n - b*49;
    for (int idx = tid; idx < 9*544; idx += NTHREADS) {
        int j   = idx / 544;
        int c   = idx - j*544;
        int t9  = 9*m + j;
        int khw = t9 / 49;
        int oyx = t9 - khw*49;
        int oy  = oyx / 7;
        int ox  = oyx - oy*7;
        int kh  = khw / 3;
        int kw  = khw - kh*3;
        int h   = 2*oy + kh;
        int w   = 2*ox + kw;
        float v = x[(size_t)(((b*16 + h)*16) + w)*544 + c];
        if (c < 512) sP[j*512 + c] = v;           // k = j*32 + c/16, s = c%16
        else         sA[j*32 + (c - 512)] = v;    // k = j*32 + (c-512)
    }
    for (int i = tid; i < KK*OC; i += NTHREADS) sR[i] = 1.0f/OC;
    __syncthreads();

    // ---- Phase 1: votes  v[k,o,i*4+m] = sum_j p[k,i*4+j] * W[k,o,j*4+m] ----
    float* vbase = g_votes + (size_t)n * (KK*OSZ);
    for (int pair = tid; pair < KK*OC; pair += NTHREADS) {
        int k = pair >> 5;
        const float* p = sP + k*PS;
        const float4* wv4 = (const float4*)(wts + (size_t)pair*16);
        float w0[16];
        #pragma unroll
        for (int q = 0; q < 4; ++q) {
            float4 t = wv4[q];
            w0[4*q+0]=t.x; w0[4*q+1]=t.y; w0[4*q+2]=t.z; w0[4*q+3]=t.w;
        }
        float4* dst = (float4*)(vbase + (size_t)pair*16);
        #pragma unroll
        for (int i = 0; i < 4; ++i) {
            float p0=p[i*4+0], p1=p[i*4+1], p2=p[i*4+2], p3=p[i*4+3];
            float4 r;
            r.x = p0*w0[0] + p1*w0[4] + p2*w0[8]  + p3*w0[12];
            r.y = p0*w0[1] + p1*w0[5] + p2*w0[9]  + p3*w0[13];
            r.z = p0*w0[2] + p1*w0[6] + p2*w0[10] + p3*w0[14];
            r.w = p0*w0[3] + p1*w0[7] + p2*w0[11] + p3*w0[15];
            dst[i] = r;
        }
    }
    __syncthreads();

    // ---- EM routing: 3 iterations ----
    float lam = 0.001f;
    for (int it = 0; it < 3; ++it) {
        lam += 0.0001f;

        // (a) r <- (r*a) normalized over o; accumulate rsum[o]
        if (tid < 32) sRsum[tid] = 0.f;
        __syncthreads();
        {
            float acc = 0.f;
            for (int k = wid; k < KK; k += 16) {
                float rr = sR[k*32 + lane] * sA[k];
                float s = rr;
                #pragma unroll
                for (int off = 16; off; off >>= 1)
                    s += __shfl_xor_sync(0xffffffffu, s, off);
                float rh = rr / (s + CEPS);
                sR[k*32 + lane] = rh;
                acc += rh;
            }
            atomicAdd(&sRsum[lane], acc);
        }
        __syncthreads();
        if (tid < 32) {
            float rs = sRsum[tid];
            sIRs[tid] = 1.f/(rs + CEPS);
            sS1[tid]  = rs/(rs + CEPS);
        }
        __syncthreads();

        // (b) vote pass: mean & E[v^2] in ONE pass; then std/cost/act_out
        {
            const int os = tid;          // blockDim == 512 exactly
            const int o  = os >> 4;
            const int s  = os & 15;
            const float irs = sIRs[o];
            const float* vp  = vbase + os;
            const float* rp0 = sR + o;
            float accM = 0.f, accQ = 0.f;
            #pragma unroll 4
            for (int k = 0; k < KK; ++k) {
                float v  = vp[k*512];
                float rp = rp0[k*32] * irs;
                accM += rp*v;
                accQ += rp*v*v;
            }
            float mean = accM;
            // sum rp*(v-mean)^2 = Q - mean^2*(2 - S1)   (exact, S1 = rsum/(rsum+eps))
            float var = accQ - mean*mean*(2.f - sS1[o]);
            var = fmaxf(var, 0.f) + CEPS;         // = std^2
            float logstd = 0.5f*logf(var);
            sMean[o*17 + s] = mean;
            sIv[o*17 + s]   = 0.5f/var;           // 1/(2 std^2)
            float sl = logstd;                    // segment-16 sum of log std
            #pragma unroll
            for (int off = 8; off; off >>= 1)
                sl += __shfl_xor_sync(0xffffffffu, sl, off);
            if (s == 0) {
                float cost = (16.f*beta_u[o] + sl) * sRsum[o];
                float z = lam * (beta_a[o] - cost);
                float a = 1.f/(1.f + expf(-z));
                sAct[o] = a;
                sC[o]   = logf(a) - sl - 8.f*LN2PI;
            }
        }
        __syncthreads();

        if (it == 2) break;

        // (c) e-step: ln_ap[k,o] = C[o] - sum_s (v-mean)^2 * iv ; softmax over o
        {
            float mreg[16], ivreg[16];
            #pragma unroll
            for (int q = 0; q < 16; ++q) {
                mreg[q]  = sMean[lane*17 + q];
                ivreg[q] = sIv[lane*17 + q];
            }
            const float Co = sC[lane];
            for (int k = wid; k < KK; k += 16) {
                const float4* v4 = (const float4*)(vbase + (size_t)(k*32 + lane)*16);
                float acc = 0.f;
                #pragma unroll
                for (int q = 0; q < 4; ++q) {
                    float4 v = v4[q];
                    float d0 = v.x - mreg[4*q+0];
                    float d1 = v.y - mreg[4*q+1];
                    float d2 = v.z - mreg[4*q+2];
                    float d3 = v.w - mreg[4*q+3];
                    acc += d0*d0*ivreg[4*q+0] + d1*d1*ivreg[4*q+1]
                         + d2*d2*ivreg[4*q+2] + d3*d3*ivreg[4*q+3];
                }
                float lnap = Co - acc;
                float mx = lnap;
                #pragma unroll
                for (int off = 16; off; off >>= 1)
                    mx = fmaxf(mx, __shfl_xor_sync(0xffffffffu, mx, off));
                float e  = expf(lnap - mx);
                float se = e;
                #pragma unroll
                for (int off = 16; off; off >>= 1)
                    se += __shfl_xor_sync(0xffffffffu, se, off);
                sR[k*32 + lane] = e/se;
            }
        }
        __syncthreads();
    }

    // ---- output: [n, 544] = concat(mean[32*16], act[32]) ----
    {
        int o = tid >> 4, s = tid & 15;
        out[(size_t)n*544 + tid] = sMean[o*17 + s];
        if (tid < 32)
            out[(size_t)n*544 + 512 + tid] = sAct[tid];
    }
}

extern "C" void kernel_launch(void* const* d_in, const int* in_sizes, int n_in,
                              void* d_out, int out_size)
{
    const float* x  = (const float*)d_in[0];
    const float* w  = (const float*)d_in[1];
    const float* bu = (const float*)d_in[2];
    const float* ba = (const float*)d_in[3];
    float* out = (float*)d_out;

    // ~62 KB used; request 130 KB to cap occupancy at 1 CTA/SM so each wave's
    // vote working set (148 * 576 KB = 85 MB) stays L2-resident.
    const int smem_bytes = 133120;
    cudaFuncSetAttribute(convcaps_kernel,
                         cudaFuncAttributeMaxDynamicSharedMemorySize, smem_bytes);
    convcaps_kernel<<<NPOS, NTHREADS, smem_bytes>>>(x, w, bu, ba, out);
}

// round 2
// speedup vs baseline: 2.0021x; 2.0021x over previous
#include <cuda_runtime.h>
#include <cuda_fp16.h>
#include <math.h>

#define NPOS 392
#define KK   288          // K*K*IN_CAPS
#define OC   32
#define PS   16
#define OSZ  512          // OC*PS
#define CEPS 1e-8f
#define LN2PI 1.8378770664093453f
#define NTHREADS 512
#define KH    144         // KK/2

// vote scratch (fp16): 392 * 288 * 512 * 2B = 115.6 MB
__device__ __half g_votes[(size_t)NPOS * KK * OSZ];

extern __shared__ float smem[];

__global__ __launch_bounds__(NTHREADS, 2)
void convcaps_kernel(const float* __restrict__ x,
                     const float* __restrict__ wts,
                     const float* __restrict__ beta_u,
                     const float* __restrict__ beta_a,
                     float* __restrict__ out)
{
    const int n    = blockIdx.x;
    const int tid  = threadIdx.x;
    const int lane = tid & 31;
    const int wid  = tid >> 5;

    // ---- smem carve (16384 floats = 64 KB exactly) ----
    float* sP    = smem;            // 4608  poses [k][s]
    float* sA    = sP + KK*PS;      // 288   acts
    float* sR    = sA + KK;         // 9216  r [k][o]
    float* sMean = sR + KK*OC;      // 544   mean [o*17+s]
    float* sIv   = sMean + 544;     // 544   1/(2 std^2)
    float* sRsum = sIv + 544;       // 32
    float* sIRs  = sRsum + 32;      // 32
    float* sS1   = sIRs + 32;       // 32
    float* sAct  = sS1 + 32;        // 32
    float* sC    = sAct + 32;       // 32
    float* sPart = sC + 32;         // 1024  k-half partials [idx][4]

    // ---- Phase 0: gather input tile (matches reference reshape semantics) ----
    const int b = n / 49;
    const int m = n - b*49;
    for (int idx = tid; idx < 9*544; idx += NTHREADS) {
        int j   = idx / 544;
        int c   = idx - j*544;
        int t9  = 9*m + j;
        int khw = t9 / 49;
        int oyx = t9 - khw*49;
        int oy  = oyx / 7;
        int ox  = oyx - oy*7;
        int kh  = khw / 3;
        int kw  = khw - kh*3;
        int h   = 2*oy + kh;
        int w   = 2*ox + kw;
        float v = x[(size_t)(((b*16 + h)*16) + w)*544 + c];
        if (c < 512) sP[j*512 + c] = v;
        else         sA[j*32 + (c - 512)] = v;
    }
    for (int i = tid; i < KK*OC; i += NTHREADS) sR[i] = 1.0f/OC;
    __syncthreads();

    // ---- Phase 1: votes v[k,o,:] = p[k,:] (4x4) @ W[k,o] (4x4), fp16 store ----
    __half* vbase = g_votes + (size_t)n * (KK*OSZ);
    for (int pair = tid; pair < KK*OC; pair += NTHREADS) {
        int k = pair >> 5;
        const float* p = sP + k*PS;
        const float4* wv4 = (const float4*)(wts + (size_t)pair*16);
        float w0[16];
        #pragma unroll
        for (int q = 0; q < 4; ++q) {
            float4 t = wv4[q];
            w0[4*q+0]=t.x; w0[4*q+1]=t.y; w0[4*q+2]=t.z; w0[4*q+3]=t.w;
        }
        __half2 hh[8];
        #pragma unroll
        for (int i = 0; i < 4; ++i) {
            float p0=p[i*4+0], p1=p[i*4+1], p2=p[i*4+2], p3=p[i*4+3];
            float r0 = p0*w0[0] + p1*w0[4] + p2*w0[8]  + p3*w0[12];
            float r1 = p0*w0[1] + p1*w0[5] + p2*w0[9]  + p3*w0[13];
            float r2 = p0*w0[2] + p1*w0[6] + p2*w0[10] + p3*w0[14];
            float r3 = p0*w0[3] + p1*w0[7] + p2*w0[11] + p3*w0[15];
            hh[2*i+0] = __floats2half2_rn(r0, r1);
            hh[2*i+1] = __floats2half2_rn(r2, r3);
        }
        uint4* dst = (uint4*)(vbase + (size_t)pair*16);
        uint4 u0, u1;
        u0.x = *(unsigned*)&hh[0]; u0.y = *(unsigned*)&hh[1];
        u0.z = *(unsigned*)&hh[2]; u0.w = *(unsigned*)&hh[3];
        u1.x = *(unsigned*)&hh[4]; u1.y = *(unsigned*)&hh[5];
        u1.z = *(unsigned*)&hh[6]; u1.w = *(unsigned*)&hh[7];
        dst[0] = u0; dst[1] = u1;
    }
    __syncthreads();

    // ---- EM routing: 3 iterations ----
    float lam = 0.001f;
    for (int it = 0; it < 3; ++it) {
        lam += 0.0001f;

        // (a) r <- (r*a) normalized over o; accumulate rsum[o]
        if (tid < 32) sRsum[tid] = 0.f;
        __syncthreads();
        {
            float acc = 0.f;
            for (int k = wid; k < KK; k += 16) {
                float rr = sR[k*32 + lane] * sA[k];
                float s = rr;
                #pragma unroll
                for (int off = 16; off; off >>= 1)
                    s += __shfl_xor_sync(0xffffffffu, s, off);
                float rh = rr / (s + CEPS);
                sR[k*32 + lane] = rh;
                acc += rh;
            }
            atomicAdd(&sRsum[lane], acc);
        }
        __syncthreads();
        if (tid < 32) {
            float rs = sRsum[tid];
            sIRs[tid] = 1.f/(rs + CEPS);
            sS1[tid]  = rs/(rs + CEPS);
        }
        __syncthreads();

        // (b) m-step vote pass: k split in halves across the block.
        //     thread: khalf = tid>>8, idx = tid&255, o = idx>>3, sp = idx&7
        {
            const int khalf = tid >> 8;
            const int idx   = tid & 255;
            const int o     = idx >> 3;
            const int sp    = idx & 7;
            const __half2* vp2 = (const __half2*)vbase + idx;
            const float* rp0 = sR + o;
            float m0 = 0.f, m1 = 0.f, q0 = 0.f, q1 = 0.f;
            const int k0 = khalf * KH;
            #pragma unroll 4
            for (int k = k0; k < k0 + KH; ++k) {
                float2 v = __half22float2(vp2[(size_t)k*256]);
                float r  = rp0[k*32];
                m0 += r*v.x; m1 += r*v.y;
                q0 += r*v.x*v.x; q1 += r*v.y*v.y;
            }
            if (khalf) {
                float* pp = sPart + idx*4;
                pp[0]=m0; pp[1]=m1; pp[2]=q0; pp[3]=q1;
            }
            __syncthreads();
            if (!khalf) {
                const float* pp = sPart + idx*4;
                const float irs = sIRs[o];
                m0 = (m0 + pp[0]) * irs;
                m1 = (m1 + pp[1]) * irs;
                q0 = (q0 + pp[2]) * irs;
                q1 = (q1 + pp[3]) * irs;
                float s1 = sS1[o];
                // sum rp*(v-mean)^2 = Q - mean^2*(2 - S1)  (exact with EPS algebra)
                float v0 = fmaxf(q0 - m0*m0*(2.f - s1), 0.f) + CEPS;
                float v1 = fmaxf(q1 - m1*m1*(2.f - s1), 0.f) + CEPS;
                sMean[o*17 + 2*sp]     = m0;
                sMean[o*17 + 2*sp + 1] = m1;
                sIv[o*17 + 2*sp]       = 0.5f/v0;
                sIv[o*17 + 2*sp + 1]   = 0.5f/v1;
                float sl = 0.5f*(__logf(v0) + __logf(v1));  // logstd pair-sum
                #pragma unroll
                for (int off = 1; off < 8; off <<= 1)
                    sl += __shfl_xor_sync(0xffffffffu, sl, off);
                if (sp == 0) {
                    float cost = (16.f*beta_u[o] + sl) * sRsum[o];
                    float z = lam * (beta_a[o] - cost);
                    float a = 1.f/(1.f + __expf(-z));
                    sAct[o] = a;
                    sC[o]   = __logf(a) - sl - 8.f*LN2PI;
                }
            }
        }
        __syncthreads();

        if (it == 2) break;

        // (c) e-step: ln_ap[k,o] = C[o] - sum_s (v-mean)^2 * iv; softmax over o
        {
            float mreg[16], ivreg[16];
            #pragma unroll
            for (int q = 0; q < 16; ++q) {
                mreg[q]  = sMean[lane*17 + q];
                ivreg[q] = sIv[lane*17 + q];
            }
            const float Co = sC[lane];
            const uint4* vr = (const uint4*)vbase;
            for (int k = wid; k < KK; k += 16) {
                uint4 u0 = vr[(size_t)(k*32 + lane)*2];
                uint4 u1 = vr[(size_t)(k*32 + lane)*2 + 1];
                float acc = 0.f;
                #pragma unroll
                for (int h = 0; h < 8; ++h) {
                    unsigned u = (h < 4) ? ((const unsigned*)&u0)[h]
                                         : ((const unsigned*)&u1)[h-4];
                    float2 f = __half22float2(*(__half2*)&u);
                    float d0 = f.x - mreg[2*h];
                    float d1 = f.y - mreg[2*h+1];
                    acc += d0*d0*ivreg[2*h] + d1*d1*ivreg[2*h+1];
                }
                float lnap = Co - acc;
                float mx = lnap;
                #pragma unroll
                for (int off = 16; off; off >>= 1)
                    mx = fmaxf(mx, __shfl_xor_sync(0xffffffffu, mx, off));
                float e  = __expf(lnap - mx);
                float se = e;
                #pragma unroll
                for (int off = 16; off; off >>= 1)
                    se += __shfl_xor_sync(0xffffffffu, se, off);
                sR[k*32 + lane] = e/se;
            }
        }
        __syncthreads();
    }

    // ---- output: [n, 544] = concat(mean[32*16], act[32]) ----
    {
        int o = tid >> 4, s = tid & 15;
        out[(size_t)n*544 + tid] = sMean[o*17 + s];
        if (tid < 32)
            out[(size_t)n*544 + 512 + tid] = sAct[tid];
    }
}

extern "C" void kernel_launch(void* const* d_in, const int* in_sizes, int n_in,
                              void* d_out, int out_size)
{
    const float* x  = (const float*)d_in[0];
    const float* w  = (const float*)d_in[1];
    const float* bu = (const float*)d_in[2];
    const float* ba = (const float*)d_in[3];
    float* out = (float*)d_out;

    const int smem_bytes = 16384 * 4;   // 64 KB -> 2 CTAs/SM
    cudaFuncSetAttribute(convcaps_kernel,
                         cudaFuncAttributeMaxDynamicSharedMemorySize, smem_bytes);
    convcaps_kernel<<<NPOS, NTHREADS, smem_bytes>>>(x, w, bu, ba, out);
}